// round 9
// baseline (speedup 1.0000x reference)
#include <cuda_runtime.h>
#include <cstdint>
#include <math.h>

#define LSEQ 99
#define HID  1536
#define G4   6144
#define GRID 128
#define NT   256
#define JPB  12

__device__ float d_X[198 * HID];
__device__ float d_preAct[198 * G4];
__device__ float d_t0[HID];
__device__ float d_tpos[HID];
__device__ float d_Cw[LSEQ * 256];
__device__ float d_D0[256];
__device__ float d_D1[256];
__device__ float d_base[256];
__device__ float d_Bh[256];
__device__ float d_h[2][HID];
__device__ float4 d_rng[LSEQ];
__device__ unsigned d_bar_cnt;
__device__ volatile unsigned d_bar_gen;

__device__ __forceinline__ float sigf(float x) { return 1.0f / (1.0f + expf(-x)); }

__device__ __forceinline__ void tf2x32(unsigned k0, unsigned k1,
                                       unsigned x0, unsigned x1,
                                       unsigned& o0, unsigned& o1) {
    unsigned ks2 = k0 ^ k1 ^ 0x1BD11BDAu;
    x0 += k0; x1 += k1;
#define TFR(r) { x0 += x1; x1 = (x1 << (r)) | (x1 >> (32 - (r))); x1 ^= x0; }
    TFR(13) TFR(15) TFR(26) TFR(6)
    x0 += k1;  x1 += ks2 + 1u;
    TFR(17) TFR(29) TFR(16) TFR(24)
    x0 += ks2; x1 += k0 + 2u;
    TFR(13) TFR(15) TFR(26) TFR(6)
    x0 += k0;  x1 += k1 + 3u;
    TFR(17) TFR(29) TFR(16) TFR(24)
    x0 += k1;  x1 += ks2 + 4u;
    TFR(13) TFR(15) TFR(26) TFR(6)
    x0 += ks2; x1 += k0 + 5u;
#undef TFR
    o0 = x0; o1 = x1;
}

__device__ __forceinline__ float u01(unsigned b) {
    return __uint_as_float((b >> 9) | 0x3f800000u) - 1.0f;
}
__device__ __forceinline__ float gumbelf(unsigned b) {
    const float TINY = 1.17549435e-38f;
    float u = u01(b) * (1.0f - TINY) + TINY;
    u = fmaxf(TINY, u);
    return -logf(-logf(u));
}
// partitionable counter-mode 32-bit random bits: tf(key, 0, i).o0 ^ o1
__device__ __forceinline__ unsigned pbits(unsigned k0, unsigned k1, unsigned i) {
    unsigned a, b;
    tf2x32(k0, k1, 0u, i, a, b);
    return a ^ b;
}

__global__ void rng_kernel() {
    int t = threadIdx.x;
    if (t >= LSEQ) return;
    // keys = split(key(42), 99)  [partitionable]: key_t = tf((0,42), 0, t)
    unsigned kA, kB;
    tf2x32(0u, 42u, 0u, (unsigned)t, kA, kB);
    // k1,k2,k3 = split(key_t, 3): k_i = tf(key_t, 0, i)
    unsigned k1a, k1b, k2a, k2b, k3a, k3b;
    tf2x32(kA, kB, 0u, 0u, k1a, k1b);
    tf2x32(kA, kB, 0u, 1u, k2a, k2b);
    tf2x32(kA, kB, 0u, 2u, k3a, k3b);
    // t = uniform(k1), scalar
    float tu = fmaxf(0.0f, u01(pbits(k1a, k1b, 0u)));
    // gumbel(k2, (2,)): element i uses counter i
    float ga = gumbelf(pbits(k2a, k2b, 0u));
    float gb = gumbelf(pbits(k2a, k2b, 1u));
    // randint(k3, (), 0, 2): khi,klo = split(k3,2); lower_bits & 1
    unsigned loa, lob, hia, hib;
    tf2x32(k3a, k3b, 0u, 0u, hia, hib);
    tf2x32(k3a, k3b, 0u, 1u, loa, lob);
    int r = (int)(pbits(loa, lob, 0u) & 1u);
    d_rng[t] = make_float4(tu, ga, gb, __int_as_float(r));
}

__global__ void prep_kernel(const float* __restrict__ sents,
                            const int* __restrict__ masks,
                            const float* __restrict__ pos) {
    int e = blockIdx.x * blockDim.x + threadIdx.x;
    if (e >= HID) return;
    float s = 0.f, sp = 0.f, ms = 0.f;
    for (int t = 0; t < LSEQ; t++) {
        float m = (float)masks[t];
        float sv = sents[t * HID + e], pv = pos[t * HID + e];
        s += sv * m; sp += pv * m; ms += m;
        d_X[t * HID + e] = sv;
        d_X[(LSEQ + t) * HID + e] = sv + pv;
    }
    d_t0[e] = s / ms; d_tpos[e] = sp / ms;
}

// preAct[m][n] = X[m,:]·W_ih[n,:] + b_ih[n] + b_hh[n];  M=198 N=6144 K=1536
__global__ __launch_bounds__(256) void gemm_preact(const float* __restrict__ W,
                                                   const float* __restrict__ bih,
                                                   const float* __restrict__ bhh) {
    __shared__ float As[16][68];
    __shared__ float Bs[16][68];
    int bn = blockIdx.x * 64, bm = blockIdx.y * 64;
    int tid = threadIdx.x, tx = tid % 16, ty = tid / 16;
    int lr = tid / 4, lc = tid % 4;
    float acc[4][4] = {};
    for (int k0 = 0; k0 < HID; k0 += 16) {
        int gm = bm + lr;
        float4 av = (gm < 198) ? *(const float4*)(d_X + (size_t)gm * HID + k0 + lc * 4)
                               : make_float4(0.f, 0.f, 0.f, 0.f);
        float4 bv = *(const float4*)(W + (size_t)(bn + lr) * HID + k0 + lc * 4);
        As[lc*4+0][lr] = av.x; As[lc*4+1][lr] = av.y; As[lc*4+2][lr] = av.z; As[lc*4+3][lr] = av.w;
        Bs[lc*4+0][lr] = bv.x; Bs[lc*4+1][lr] = bv.y; Bs[lc*4+2][lr] = bv.z; Bs[lc*4+3][lr] = bv.w;
        __syncthreads();
#pragma unroll
        for (int k = 0; k < 16; k++) {
            float a[4], bb[4];
#pragma unroll
            for (int i = 0; i < 4; i++) { a[i] = As[k][ty*4+i]; bb[i] = Bs[k][tx*4+i]; }
#pragma unroll
            for (int i = 0; i < 4; i++)
#pragma unroll
                for (int j = 0; j < 4; j++) acc[i][j] += a[i] * bb[j];
        }
        __syncthreads();
    }
#pragma unroll
    for (int i = 0; i < 4; i++) {
        int m = bm + ty * 4 + i;
        if (m < 198)
#pragma unroll
            for (int j = 0; j < 4; j++) {
                int n = bn + tx * 4 + j;
                d_preAct[(size_t)m * G4 + n] = acc[i][j] + bih[n] + bhh[n];
            }
    }
}

// block t<99: Cw[t][j]=W1[j,3072:4608]·word_t ; t==99: D0 ; t==100: D1
__global__ __launch_bounds__(256) void proj_kernel(const float* __restrict__ W1) {
    __shared__ float4 xs4[384];
    int t = blockIdx.x, tid = threadIdx.x;
    const float* src = (t < 99) ? (d_X + (size_t)(99 + t) * HID)
                                : (t == 99 ? d_t0 : d_tpos);
    int colofs = (t < 99) ? 3072 : 4608;
    for (int i = tid; i < 384; i += 256) xs4[i] = ((const float4*)src)[i];
    __syncthreads();
    int w = tid >> 5, lane = tid & 31;
    for (int j = w; j < 256; j += 8) {
        const float4* wr = (const float4*)(W1 + (size_t)j * G4 + colofs);
        float acc = 0.f;
#pragma unroll
        for (int it = 0; it < 12; it++) {
            float4 a = wr[it * 32 + lane], x = xs4[it * 32 + lane];
            acc += a.x*x.x + a.y*x.y + a.z*x.z + a.w*x.w;
        }
#pragma unroll
        for (int o = 16; o; o >>= 1) acc += __shfl_xor_sync(~0u, acc, o);
        if (!lane) {
            if (t < 99) d_Cw[t * 256 + j] = acc;
            else if (t == 99) d_D0[j] = acc;
            else d_D1[j] = acc;
        }
    }
}

__device__ __forceinline__ void gridbar(unsigned& gen) {
    gen++;
    __syncthreads();
    if (threadIdx.x == 0) {
        __threadfence();
        unsigned arr = atomicAdd(&d_bar_cnt, 1u);
        if (arr == GRID - 1) { d_bar_cnt = 0; __threadfence(); d_bar_gen = gen; }
        else { while (d_bar_gen < gen) {} }
        __threadfence();
    }
    __syncthreads();
}

__device__ __forceinline__ void lstm_dots(const float* __restrict__ Whh, int j0,
                                          int w, int lane, const float4* hv,
                                          float* dots) {
#pragma unroll
    for (int r = 0; r < 6; r++) {
        int fi = w * 6 + r, unit = fi >> 2, gate = fi & 3;
        const float4* wr = (const float4*)(Whh + ((size_t)gate * HID + j0 + unit) * HID);
        float acc = 0.f;
#pragma unroll
        for (int it = 0; it < 12; it++) {
            float4 a = __ldcg(wr + it * 32 + lane), x = hv[it * 32 + lane];
            acc += a.x*x.x + a.y*x.y + a.z*x.z + a.w*x.w;
        }
#pragma unroll
        for (int o = 16; o; o >>= 1) acc += __shfl_xor_sync(~0u, acc, o);
        if (!lane) dots[fi] = acc;
    }
}

__device__ __forceinline__ float dot1536(const float* __restrict__ wrow,
                                         const float4* hv, int lane) {
    const float4* wr = (const float4*)wrow;
    float acc = 0.f;
#pragma unroll
    for (int it = 0; it < 12; it++) {
        float4 a = __ldcg(wr + it * 32 + lane), x = hv[it * 32 + lane];
        acc += a.x*x.x + a.y*x.y + a.z*x.z + a.w*x.w;
    }
#pragma unroll
    for (int o = 16; o; o >>= 1) acc += __shfl_xor_sync(~0u, acc, o);
    return acc;
}

__global__ __launch_bounds__(NT, 1) void core_kernel(
    const float* __restrict__ Whh, const float* __restrict__ W1,
    const float* __restrict__ b1,  const float* __restrict__ W2,
    const float* __restrict__ b2,  const float* __restrict__ Wl,
    const float* __restrict__ bl,  const int* __restrict__ labels,
    float* __restrict__ out) {
    __shared__ float4 hs4[384];
    __shared__ float dots[48];
    __shared__ float cst[JPB];
    __shared__ float red0[8], red1[8];
    __shared__ float lg[3];
    const int tid = threadIdx.x, b = blockIdx.x, w = tid >> 5, lane = tid & 31;
    const int j0 = b * JPB;
    unsigned gen = 0;
    int cur = 0;

    if (tid < JPB) { cst[tid] = 0.f; d_h[0][j0 + tid] = 0.f; d_h[1][j0 + tid] = 0.f; }
    if (b == 0) d_Bh[tid] = 0.f;
    gridbar(gen);

    // ---------- chain A (input = sent, preAct rows 0..98) ----------
    for (int t = 0; t < LSEQ; t++) {
        const float4* hin = (const float4*)d_h[cur];
        for (int i = tid; i < 384; i += NT) hs4[i] = __ldcg(hin + i);
        __syncthreads();
        lstm_dots(Whh, j0, w, lane, hs4, dots);
        __syncthreads();
        if (tid < JPB) {
            int j = j0 + tid;
            const float* pa = d_preAct + (size_t)t * G4;
            float gi = pa[j] + dots[tid*4+0], gf = pa[HID+j] + dots[tid*4+1];
            float gg = pa[2*HID+j] + dots[tid*4+2], go = pa[3*HID+j] + dots[tid*4+3];
            float c2 = sigf(gf) * cst[tid] + sigf(gi) * tanhf(gg);
            cst[tid] = c2;
            d_h[cur ^ 1][j] = sigf(go) * tanhf(c2);
        }
        cur ^= 1;
        gridbar(gen);
    }

    // ---------- base = W1[:, :1536]@overall + b1 + D0 ; reset state ----------
    {
        const float4* hin = (const float4*)d_h[cur];
        for (int i = tid; i < 384; i += NT) hs4[i] = __ldcg(hin + i);
        __syncthreads();
        if (w < 2) {
            int j = 2 * b + w;
            float acc = dot1536(W1 + (size_t)j * G4, hs4, lane);
            if (!lane) d_base[j] = acc + b1[j] + d_D0[j];
        }
        if (tid < JPB) {
            cst[tid] = 0.f; d_h[0][j0 + tid] = 0.f; d_h[1][j0 + tid] = 0.f;
        }
        gridbar(gen);
    }
    cur = 0;

    // ---------- chain B with policy ----------
    float asum = 0.f;
    int dirty = 0;
    for (int t = 0; t < LSEQ; t++) {
        if (dirty) {
            const float4* hin = (const float4*)d_h[cur];
            for (int i = tid; i < 384; i += NT) hs4[i] = __ldcg(hin + i);
            __syncthreads();
            if (w < 2) {
                int j = 2 * b + w;
                float acc = dot1536(W1 + (size_t)j * G4 + HID, hs4, lane);
                if (!lane) d_Bh[j] = acc;
            }
            gridbar(gen);
        }
        // policy (computed redundantly & identically by every block)
        float4 r4 = d_rng[t];
        float z = d_base[tid] + d_Bh[tid] + d_Cw[t * 256 + tid]
                + (float)(t + 1) * d_D1[tid];
        float u = sigf(z);
        float p0 = u * W2[tid], p1 = u * W2[256 + tid];
#pragma unroll
        for (int o = 16; o; o >>= 1) {
            p0 += __shfl_xor_sync(~0u, p0, o);
            p1 += __shfl_xor_sync(~0u, p1, o);
        }
        if (!lane) { red0[w] = p0; red1[w] = p1; }
        __syncthreads();
        float l0 = 0.f, l1 = 0.f;
#pragma unroll
        for (int i = 0; i < 8; i++) { l0 += red0[i]; l1 += red1[i]; }
        __syncthreads();
        l0 = sigf(l0 + b2[0]); l1 = sigf(l1 + b2[1]);
        float mx = fmaxf(l0, l1);
        float e0 = expf(l0 - mx), e1 = expf(l1 - mx);
        float lden = logf(e0 + e1);
        float lp0 = l0 - mx - lden, lp1 = l1 - mx - lden;
        int a;
        if (r4.x > 0.1f) a = (lp1 + r4.z > lp0 + r4.y) ? 1 : 0;
        else a = __float_as_int(r4.w);
        asum += (float)a;
        if (b == 0 && tid == 0) out[3 + t] = (float)a;
        if (a == 1) {
            const float4* hin = (const float4*)d_h[cur];
            for (int i = tid; i < 384; i += NT) hs4[i] = __ldcg(hin + i);
            __syncthreads();
            lstm_dots(Whh, j0, w, lane, hs4, dots);
            __syncthreads();
            if (tid < JPB) {
                int j = j0 + tid;
                const float* pa = d_preAct + (size_t)(99 + t) * G4;
                float gi = pa[j] + dots[tid*4+0], gf = pa[HID+j] + dots[tid*4+1];
                float gg = pa[2*HID+j] + dots[tid*4+2], go = pa[3*HID+j] + dots[tid*4+3];
                float c2 = sigf(gf) * cst[tid] + sigf(gi) * tanhf(gg);
                cst[tid] = c2;
                d_h[cur ^ 1][j] = sigf(go) * tanhf(c2);
            }
            cur ^= 1; dirty = 1;
            gridbar(gen);
        } else dirty = 0;
    }

    gridbar(gen);
    // ---------- epilogue: pred + loss (block 0) ----------
    if (b == 0) {
        const float4* hin = (const float4*)d_h[cur];
        for (int i = tid; i < 384; i += NT) hs4[i] = __ldcg(hin + i);
        __syncthreads();
        if (w < 3) {
            float acc = dot1536(Wl + (size_t)w * HID, hs4, lane);
            if (!lane) lg[w] = acc + bl[w];
        }
        __syncthreads();
        if (tid == 0) {
            float m = fmaxf(lg[0], fmaxf(lg[1], lg[2]));
            float e0 = expf(lg[0]-m), e1 = expf(lg[1]-m), e2 = expf(lg[2]-m);
            float lse = m + logf(e0 + e1 + e2);
            float pr[3] = { lg[0]-lse, lg[1]-lse, lg[2]-lse };
            out[0] = pr[0]; out[1] = pr[1]; out[2] = pr[2];
            int lb = labels[0];
            float nll = -pr[lb];
            float reward = ((float)LSEQ - asum) / (float)LSEQ;
            out[102] = 2.0f * nll * (0.001f + reward);
        }
    }
}

extern "C" void kernel_launch(void* const* d_in, const int* in_sizes, int n_in,
                              void* d_out, int out_size) {
    const float* sents = (const float*)d_in[0];
    const int*   masks = (const int*)d_in[1];
    const int*   labels= (const int*)d_in[2];
    const float* W_ih  = (const float*)d_in[3];
    const float* W_hh  = (const float*)d_in[4];
    const float* b_ih  = (const float*)d_in[5];
    const float* b_hh  = (const float*)d_in[6];
    const float* W1    = (const float*)d_in[7];
    const float* b1    = (const float*)d_in[8];
    const float* W2    = (const float*)d_in[9];
    const float* b2    = (const float*)d_in[10];
    const float* Wl    = (const float*)d_in[11];
    const float* bl    = (const float*)d_in[12];
    const float* pos   = (const float*)d_in[13];
    float* out = (float*)d_out;

    void* p;
    cudaGetSymbolAddress(&p, d_bar_cnt);
    cudaMemsetAsync(p, 0, sizeof(unsigned));
    cudaGetSymbolAddress(&p, (const void*)&d_bar_gen);
    cudaMemsetAsync(p, 0, sizeof(unsigned));

    prep_kernel<<<6, 256>>>(sents, masks, pos);
    rng_kernel<<<1, 128>>>();
    dim3 gg(96, 4);
    gemm_preact<<<gg, 256>>>(W_ih, b_ih, b_hh);
    proj_kernel<<<101, 256>>>(W1);
    core_kernel<<<GRID, NT>>>(W_hh, W1, b1, W2, b2, Wl, bl, labels, out);
}

// round 10
// speedup vs baseline: 1.2096x; 1.2096x over previous
#include <cuda_runtime.h>
#include <cstdint>
#include <math.h>

#define LSEQ 99
#define HID  1536
#define G4   6144
#define GRID 128
#define NT   256
#define JPB  12

__device__ float d_X[198 * HID];
__device__ float d_preAct[198 * G4];
__device__ float d_t0[HID];
__device__ float d_tpos[HID];
__device__ float d_Cw[LSEQ * 256];
__device__ float d_D0[256];
__device__ float d_D1[256];
__device__ float d_base[256];
__device__ float d_BhA[3][256];          // round-robin Bh accumulators
__device__ float d_W1bT[HID * 256];      // W1[:,1536:3072] transposed
__device__ float d_h[2][HID];
__device__ float4 d_rng[LSEQ];
__device__ unsigned d_bar_cnt;
__device__ volatile unsigned d_bar_gen;

__device__ __forceinline__ float sigf(float x) { return 1.0f / (1.0f + expf(-x)); }

__device__ __forceinline__ void tf2x32(unsigned k0, unsigned k1,
                                       unsigned x0, unsigned x1,
                                       unsigned& o0, unsigned& o1) {
    unsigned ks2 = k0 ^ k1 ^ 0x1BD11BDAu;
    x0 += k0; x1 += k1;
#define TFR(r) { x0 += x1; x1 = (x1 << (r)) | (x1 >> (32 - (r))); x1 ^= x0; }
    TFR(13) TFR(15) TFR(26) TFR(6)
    x0 += k1;  x1 += ks2 + 1u;
    TFR(17) TFR(29) TFR(16) TFR(24)
    x0 += ks2; x1 += k0 + 2u;
    TFR(13) TFR(15) TFR(26) TFR(6)
    x0 += k0;  x1 += k1 + 3u;
    TFR(17) TFR(29) TFR(16) TFR(24)
    x0 += k1;  x1 += ks2 + 4u;
    TFR(13) TFR(15) TFR(26) TFR(6)
    x0 += ks2; x1 += k0 + 5u;
#undef TFR
    o0 = x0; o1 = x1;
}

__device__ __forceinline__ float u01(unsigned b) {
    return __uint_as_float((b >> 9) | 0x3f800000u) - 1.0f;
}
__device__ __forceinline__ float gumbelf(unsigned b) {
    const float TINY = 1.17549435e-38f;
    float u = u01(b) * (1.0f - TINY) + TINY;
    u = fmaxf(TINY, u);
    return -logf(-logf(u));
}
__device__ __forceinline__ unsigned pbits(unsigned k0, unsigned k1, unsigned i) {
    unsigned a, b;
    tf2x32(k0, k1, 0u, i, a, b);
    return a ^ b;
}

__global__ void rng_kernel() {
    int t = threadIdx.x;
    if (t >= LSEQ) return;
    unsigned kA, kB;
    tf2x32(0u, 42u, 0u, (unsigned)t, kA, kB);
    unsigned k1a, k1b, k2a, k2b, k3a, k3b;
    tf2x32(kA, kB, 0u, 0u, k1a, k1b);
    tf2x32(kA, kB, 0u, 1u, k2a, k2b);
    tf2x32(kA, kB, 0u, 2u, k3a, k3b);
    float tu = fmaxf(0.0f, u01(pbits(k1a, k1b, 0u)));
    float ga = gumbelf(pbits(k2a, k2b, 0u));
    float gb = gumbelf(pbits(k2a, k2b, 1u));
    unsigned loa, lob, hia, hib;
    tf2x32(k3a, k3b, 0u, 0u, hia, hib);
    tf2x32(k3a, k3b, 0u, 1u, loa, lob);
    int r = (int)(pbits(loa, lob, 0u) & 1u);
    d_rng[t] = make_float4(tu, ga, gb, __int_as_float(r));
}

__global__ void prep_kernel(const float* __restrict__ sents,
                            const int* __restrict__ masks,
                            const float* __restrict__ pos) {
    int e = blockIdx.x * blockDim.x + threadIdx.x;
    if (e >= HID) return;
    float s = 0.f, sp = 0.f, ms = 0.f;
#pragma unroll 4
    for (int t = 0; t < LSEQ; t++) {
        float m = (float)masks[t];
        float sv = sents[t * HID + e], pv = pos[t * HID + e];
        s += sv * m; sp += pv * m; ms += m;
        d_X[t * HID + e] = sv;
        d_X[(LSEQ + t) * HID + e] = sv + pv;
    }
    d_t0[e] = s / ms; d_tpos[e] = sp / ms;
}

// W1bT[k][j] = W1[j][1536+k]
__global__ __launch_bounds__(256) void transpose_w1b(const float* __restrict__ W1) {
    __shared__ float tile[32][33];
    int k0 = blockIdx.x * 32, j0 = blockIdx.y * 32;
    int tx = threadIdx.x & 31, ty = threadIdx.x >> 5;
    for (int i = ty; i < 32; i += 8)
        tile[i][tx] = W1[(size_t)(j0 + i) * G4 + 1536 + k0 + tx];
    __syncthreads();
    for (int i = ty; i < 32; i += 8)
        d_W1bT[(size_t)(k0 + i) * 256 + j0 + tx] = tile[tx][i];
}

// preAct[m][n] = X[m,:]·W_ih[n,:] + b_ih[n] + b_hh[n];  M=198 N=6144 K=1536
__global__ __launch_bounds__(256) void gemm_preact(const float* __restrict__ W,
                                                   const float* __restrict__ bih,
                                                   const float* __restrict__ bhh) {
    __shared__ float As[16][68];
    __shared__ float Bs[16][68];
    int bn = blockIdx.x * 64, bm = blockIdx.y * 64;
    int tid = threadIdx.x, tx = tid % 16, ty = tid / 16;
    int lr = tid / 4, lc = tid % 4;
    float acc[4][4] = {};
    for (int k0 = 0; k0 < HID; k0 += 16) {
        int gm = bm + lr;
        float4 av = (gm < 198) ? *(const float4*)(d_X + (size_t)gm * HID + k0 + lc * 4)
                               : make_float4(0.f, 0.f, 0.f, 0.f);
        float4 bv = *(const float4*)(W + (size_t)(bn + lr) * HID + k0 + lc * 4);
        As[lc*4+0][lr] = av.x; As[lc*4+1][lr] = av.y; As[lc*4+2][lr] = av.z; As[lc*4+3][lr] = av.w;
        Bs[lc*4+0][lr] = bv.x; Bs[lc*4+1][lr] = bv.y; Bs[lc*4+2][lr] = bv.z; Bs[lc*4+3][lr] = bv.w;
        __syncthreads();
#pragma unroll
        for (int k = 0; k < 16; k++) {
            float4 a4 = *(const float4*)&As[k][ty * 4];
            float4 b4 = *(const float4*)&Bs[k][tx * 4];
            float a[4] = {a4.x, a4.y, a4.z, a4.w};
            float bb[4] = {b4.x, b4.y, b4.z, b4.w};
#pragma unroll
            for (int i = 0; i < 4; i++)
#pragma unroll
                for (int j = 0; j < 4; j++) acc[i][j] += a[i] * bb[j];
        }
        __syncthreads();
    }
#pragma unroll
    for (int i = 0; i < 4; i++) {
        int m = bm + ty * 4 + i;
        if (m < 198)
#pragma unroll
            for (int j = 0; j < 4; j++) {
                int n = bn + tx * 4 + j;
                d_preAct[(size_t)m * G4 + n] = acc[i][j] + bih[n] + bhh[n];
            }
    }
}

// (t<99, seg): Cw[t][j]=W1[j,3072:4608]·word_t for j in seg; t==99: D0; t==100: D1
__global__ __launch_bounds__(256) void proj_kernel(const float* __restrict__ W1) {
    __shared__ float4 xs4[384];
    int t = blockIdx.x, seg = blockIdx.y, tid = threadIdx.x;
    const float* src = (t < 99) ? (d_X + (size_t)(99 + t) * HID)
                                : (t == 99 ? d_t0 : d_tpos);
    int colofs = (t < 99) ? 3072 : 4608;
    for (int i = tid; i < 384; i += 256) xs4[i] = ((const float4*)src)[i];
    __syncthreads();
    int w = tid >> 5, lane = tid & 31;
    int j = seg * 64 + w;
    for (int r = 0; r < 8; r++, j += 8) {
        const float4* wr = (const float4*)(W1 + (size_t)j * G4 + colofs);
        float acc = 0.f;
#pragma unroll
        for (int it = 0; it < 12; it++) {
            float4 a = wr[it * 32 + lane], x = xs4[it * 32 + lane];
            acc += a.x*x.x + a.y*x.y + a.z*x.z + a.w*x.w;
        }
#pragma unroll
        for (int o = 16; o; o >>= 1) acc += __shfl_xor_sync(~0u, acc, o);
        if (!lane) {
            if (t < 99) d_Cw[t * 256 + j] = acc;
            else if (t == 99) d_D0[j] = acc;
            else d_D1[j] = acc;
        }
    }
}

__device__ __forceinline__ void gridbar(unsigned& gen) {
    gen++;
    __syncthreads();
    if (threadIdx.x == 0) {
        __threadfence();
        unsigned arr = atomicAdd(&d_bar_cnt, 1u);
        if (arr == GRID - 1) { d_bar_cnt = 0; __threadfence(); d_bar_gen = gen; }
        else { while (d_bar_gen < gen) {} }
        __threadfence();
    }
    __syncthreads();
}

// interleaved: all 72 loads independent across 6 accumulators
__device__ __forceinline__ void lstm_dots(const float* __restrict__ Whh, int j0,
                                          int w, int lane, const float4* hv,
                                          float* dots) {
    float acc[6] = {0.f, 0.f, 0.f, 0.f, 0.f, 0.f};
    const float4* rp[6];
#pragma unroll
    for (int r = 0; r < 6; r++) {
        int fi = w * 6 + r, unit = fi >> 2, gate = fi & 3;
        rp[r] = (const float4*)(Whh + ((size_t)gate * HID + j0 + unit) * HID);
    }
#pragma unroll
    for (int it = 0; it < 12; it++) {
        float4 x = hv[it * 32 + lane];
#pragma unroll
        for (int r = 0; r < 6; r++) {
            float4 a = __ldcg(rp[r] + it * 32 + lane);
            acc[r] += a.x*x.x + a.y*x.y + a.z*x.z + a.w*x.w;
        }
    }
#pragma unroll
    for (int r = 0; r < 6; r++) {
        float v = acc[r];
#pragma unroll
        for (int o = 16; o; o >>= 1) v += __shfl_xor_sync(~0u, v, o);
        if (!lane) dots[w * 6 + r] = v;
    }
}

__device__ __forceinline__ float dot1536(const float* __restrict__ wrow,
                                         const float4* hv, int lane) {
    const float4* wr = (const float4*)wrow;
    float acc = 0.f;
#pragma unroll
    for (int it = 0; it < 12; it++) {
        float4 a = __ldcg(wr + it * 32 + lane), x = hv[it * 32 + lane];
        acc += a.x*x.x + a.y*x.y + a.z*x.z + a.w*x.w;
    }
#pragma unroll
    for (int o = 16; o; o >>= 1) acc += __shfl_xor_sync(~0u, acc, o);
    return acc;
}

__global__ __launch_bounds__(NT, 1) void core_kernel(
    const float* __restrict__ Whh, const float* __restrict__ W1,
    const float* __restrict__ b1,  const float* __restrict__ W2,
    const float* __restrict__ b2,  const float* __restrict__ Wl,
    const float* __restrict__ bl,  const int* __restrict__ labels,
    float* __restrict__ out) {
    __shared__ float4 hs4[384];
    __shared__ float dots[48];
    __shared__ float cst[JPB];
    __shared__ float h2s[JPB];
    __shared__ float red0[8], red1[8];
    __shared__ float lg[3];
    const int tid = threadIdx.x, b = blockIdx.x, w = tid >> 5, lane = tid & 31;
    const int j0 = b * JPB;
    unsigned gen = 0;
    int cur = 0;

    if (tid < JPB) { cst[tid] = 0.f; d_h[0][j0 + tid] = 0.f; d_h[1][j0 + tid] = 0.f; }
    if (tid < 2) {
        d_BhA[0][2 * b + tid] = 0.f;
        d_BhA[1][2 * b + tid] = 0.f;
        d_BhA[2][2 * b + tid] = 0.f;
    }
    gridbar(gen);

    // ---------- chain A (input = sent, preAct rows 0..98) ----------
    for (int t = 0; t < LSEQ; t++) {
        const float4* hin = (const float4*)d_h[cur];
        for (int i = tid; i < 384; i += NT) hs4[i] = __ldcg(hin + i);
        __syncthreads();
        lstm_dots(Whh, j0, w, lane, hs4, dots);
        __syncthreads();
        if (tid < JPB) {
            int j = j0 + tid;
            const float* pa = d_preAct + (size_t)t * G4;
            float gi = pa[j] + dots[tid*4+0], gf = pa[HID+j] + dots[tid*4+1];
            float gg = pa[2*HID+j] + dots[tid*4+2], go = pa[3*HID+j] + dots[tid*4+3];
            float c2 = sigf(gf) * cst[tid] + sigf(gi) * tanhf(gg);
            cst[tid] = c2;
            d_h[cur ^ 1][j] = sigf(go) * tanhf(c2);
        }
        cur ^= 1;
        gridbar(gen);
    }

    // ---------- base = W1[:, :1536]@overall + b1 + D0 ; reset state ----------
    {
        const float4* hin = (const float4*)d_h[cur];
        for (int i = tid; i < 384; i += NT) hs4[i] = __ldcg(hin + i);
        __syncthreads();
        if (w < 2) {
            int j = 2 * b + w;
            float acc = dot1536(W1 + (size_t)j * G4, hs4, lane);
            if (!lane) d_base[j] = acc + b1[j] + d_D0[j];
        }
        if (tid < JPB) {
            cst[tid] = 0.f; d_h[0][j0 + tid] = 0.f; d_h[1][j0 + tid] = 0.f;
        }
        gridbar(gen);
    }
    cur = 0;

    // ---------- chain B: 1 barrier per a==1 step, fused Bh partials ----------
    float asum = 0.f;
    int bsel = 0;
    int stale = 1;                     // hs4 currently holds 'overall', must reload
    const float b20 = b2[0], b21 = b2[1];
    for (int t = 0; t < LSEQ; t++) {
        float4 r4 = d_rng[t];
        float z = d_base[tid] + d_BhA[bsel][tid] + d_Cw[t * 256 + tid]
                + (float)(t + 1) * d_D1[tid];
        float u = sigf(z);
        float p0 = u * W2[tid], p1 = u * W2[256 + tid];
#pragma unroll
        for (int o = 16; o; o >>= 1) {
            p0 += __shfl_xor_sync(~0u, p0, o);
            p1 += __shfl_xor_sync(~0u, p1, o);
        }
        if (!lane) { red0[w] = p0; red1[w] = p1; }
        __syncthreads();
        float l0 = 0.f, l1 = 0.f;
#pragma unroll
        for (int i = 0; i < 8; i++) { l0 += red0[i]; l1 += red1[i]; }
        __syncthreads();
        l0 = sigf(l0 + b20); l1 = sigf(l1 + b21);
        float mx = fmaxf(l0, l1);
        float e0 = expf(l0 - mx), e1 = expf(l1 - mx);
        float lden = logf(e0 + e1);
        float lp0 = l0 - mx - lden, lp1 = l1 - mx - lden;
        int a;
        if (r4.x > 0.1f) a = (lp1 + r4.z > lp0 + r4.y) ? 1 : 0;
        else a = __float_as_int(r4.w);
        asum += (float)a;
        if (b == 0 && tid == 0) out[3 + t] = (float)a;
        if (a == 1) {
            if (stale) {
                const float4* hin = (const float4*)d_h[cur];
                for (int i = tid; i < 384; i += NT) hs4[i] = __ldcg(hin + i);
            }
            __syncthreads();
            lstm_dots(Whh, j0, w, lane, hs4, dots);
            __syncthreads();
            if (tid < JPB) {
                int j = j0 + tid;
                const float* pa = d_preAct + (size_t)(99 + t) * G4;
                float gi = pa[j] + dots[tid*4+0], gf = pa[HID+j] + dots[tid*4+1];
                float gg = pa[2*HID+j] + dots[tid*4+2], go = pa[3*HID+j] + dots[tid*4+3];
                float c2 = sigf(gf) * cst[tid] + sigf(gi) * tanhf(gg);
                cst[tid] = c2;
                float h2 = sigf(go) * tanhf(c2);
                h2s[tid] = h2;
                d_h[cur ^ 1][j] = h2;
            }
            __syncthreads();
            // Bh partial: this block's 12 h-components vs all 256 W1b rows
            {
                float part = 0.f;
                const float* wt = d_W1bT + (size_t)j0 * 256 + tid;
#pragma unroll
                for (int uu = 0; uu < JPB; uu++)
                    part += wt[uu * 256] * h2s[uu];
                int nxt = bsel + 1; if (nxt == 3) nxt = 0;
                atomicAdd(&d_BhA[nxt][tid], part);
                int old = bsel + 2; if (old >= 3) old -= 3;
                if (tid < 2) d_BhA[old][2 * b + tid] = 0.f;
            }
            cur ^= 1;
            gridbar(gen);
            bsel = bsel + 1; if (bsel == 3) bsel = 0;
            stale = 1;
        }
    }

    // ---------- epilogue: pred + loss (block 0 only; all data published) ----------
    if (b == 0) {
        const float4* hin = (const float4*)d_h[cur];
        for (int i = tid; i < 384; i += NT) hs4[i] = __ldcg(hin + i);
        __syncthreads();
        if (w < 3) {
            float acc = dot1536(Wl + (size_t)w * HID, hs4, lane);
            if (!lane) lg[w] = acc + bl[w];
        }
        __syncthreads();
        if (tid == 0) {
            float m = fmaxf(lg[0], fmaxf(lg[1], lg[2]));
            float e0 = expf(lg[0]-m), e1 = expf(lg[1]-m), e2 = expf(lg[2]-m);
            float lse = m + logf(e0 + e1 + e2);
            float pr[3] = { lg[0]-lse, lg[1]-lse, lg[2]-lse };
            out[0] = pr[0]; out[1] = pr[1]; out[2] = pr[2];
            int lb = labels[0];
            float nll = -pr[lb];
            float reward = ((float)LSEQ - asum) / (float)LSEQ;
            out[102] = 2.0f * nll * (0.001f + reward);
        }
    }
}

extern "C" void kernel_launch(void* const* d_in, const int* in_sizes, int n_in,
                              void* d_out, int out_size) {
    const float* sents = (const float*)d_in[0];
    const int*   masks = (const int*)d_in[1];
    const int*   labels= (const int*)d_in[2];
    const float* W_ih  = (const float*)d_in[3];
    const float* W_hh  = (const float*)d_in[4];
    const float* b_ih  = (const float*)d_in[5];
    const float* b_hh  = (const float*)d_in[6];
    const float* W1    = (const float*)d_in[7];
    const float* b1    = (const float*)d_in[8];
    const float* W2    = (const float*)d_in[9];
    const float* b2    = (const float*)d_in[10];
    const float* Wl    = (const float*)d_in[11];
    const float* bl    = (const float*)d_in[12];
    const float* pos   = (const float*)d_in[13];
    float* out = (float*)d_out;

    void* p;
    cudaGetSymbolAddress(&p, d_bar_cnt);
    cudaMemsetAsync(p, 0, sizeof(unsigned));
    cudaGetSymbolAddress(&p, (const void*)&d_bar_gen);
    cudaMemsetAsync(p, 0, sizeof(unsigned));

    prep_kernel<<<6, 256>>>(sents, masks, pos);
    rng_kernel<<<1, 128>>>();
    dim3 gg(96, 4);
    gemm_preact<<<gg, 256>>>(W_ih, b_ih, b_hh);
    dim3 pg(101, 4);
    proj_kernel<<<pg, 256>>>(W1);
    dim3 tg(48, 8);
    transpose_w1b<<<tg, 256>>>(W1);
    core_kernel<<<GRID, NT>>>(W_hh, W1, b1, W2, b2, Wl, bl, labels, out);
}